// round 3
// baseline (speedup 1.0000x reference)
#include <cuda_runtime.h>

// YOLOv1 loss, GB300, fully fused single kernel.
// pred/target [8192,7,7,30] f32 -> 4 f32 scalars (loss, cls, obj, coord).

#define ELEMS 1470
#define MAXB  8192

// per-batch partials: x=noobj, y=cls, z=coord, w=obj
__device__ float4 g_partials[MAXB];
__device__ unsigned int g_done = 0;   // self-resetting completion counter

__global__ void __launch_bounds__(128)
yolo_fused(const float* __restrict__ pred, const float* __restrict__ targ,
           float* __restrict__ out, int B)
{
    int b   = blockIdx.x;
    int tid = threadIdx.x;

    __shared__ float sflag[49];                    // 1.0 if obj cell else 0.0
    __shared__ __align__(8) float spb[49][10];     // pred ch0..9
    __shared__ __align__(8) float stb[49][10];     // targ ch0..9
    __shared__ float px1[98], py1[98], px2[98], py2[98], pa[98];
    __shared__ float qx1[98], qy1[98], qx2[98], qy2[98], qa[98];
    __shared__ int   objlist[98];
    __shared__ int   cnt;
    __shared__ float red[4][4];
    __shared__ bool  amlast;

    const float* pbase = pred + (size_t)b * ELEMS;
    const float* tbase = targ + (size_t)b * ELEMS;

    if (tid == 0) cnt = 0;
    // preload per-cell obj flags (target conf channel)
    if (tid < 49) {
        float c = tbase[tid * 30 + 4];
        sflag[tid] = (c > 0.0f) ? 1.0f : 0.0f;
    }
    __syncthreads();

    float a0 = 0.0f, a1 = 0.0f, a2 = 0.0f, a3 = 0.0f;  // noobj, cls, coord, obj

    // streaming load: 735 float2 per tensor; a pair never straddles a cell.
    // box channels (0..9) -> smem; class channels (10..29) -> inline masked d^2.
    const float2* p2 = reinterpret_cast<const float2*>(pbase);
    const float2* t2 = reinterpret_cast<const float2*>(tbase);
    #pragma unroll 6
    for (int i = tid; i < 735; i += 128) {
        float2 pv = p2[i];
        float2 tv = t2[i];
        int cell = i / 15;
        int ch   = (i - cell * 15) * 2;
        if (ch < 10) {
            spb[cell][ch]     = pv.x;
            spb[cell][ch + 1] = pv.y;
            stb[cell][ch]     = tv.x;
            stb[cell][ch + 1] = tv.y;
        } else {
            float f  = sflag[cell];
            float d1 = pv.x - tv.x;
            float d2 = pv.y - tv.y;
            a1 += f * (d1 * d1 + d2 * d2);
        }
    }
    __syncthreads();

    // per-box xyxy + area, compacted obj-box list
    if (tid < 98) {
        int cell = tid >> 1;
        int off  = (tid & 1) * 5;
        {
            float cx = spb[cell][off],     cy = spb[cell][off + 1];
            float w  = spb[cell][off + 2], h  = spb[cell][off + 3];
            float x1 = cx - w * 0.5f, y1 = cy - h * 0.5f;
            float x2 = cx + w * 0.5f, y2 = cy + h * 0.5f;
            px1[tid] = x1; py1[tid] = y1; px2[tid] = x2; py2[tid] = y2;
            pa[tid]  = (x2 - x1) * (y2 - y1);
        }
        {
            float cx = stb[cell][off],     cy = stb[cell][off + 1];
            float w  = stb[cell][off + 2], h  = stb[cell][off + 3];
            float x1 = cx - w * 0.5f, y1 = cy - h * 0.5f;
            float x2 = cx + w * 0.5f, y2 = cy + h * 0.5f;
            qx1[tid] = x1; qy1[tid] = y1; qx2[tid] = x2; qy2[tid] = y2;
            qa[tid]  = (x2 - x1) * (y2 - y1);
        }
        if (sflag[cell] > 0.0f) objlist[atomicAdd(&cnt, 1)] = tid;
    }
    __syncthreads();

    // per-cell noobj confidence loss
    if (tid < 49 && sflag[tid] == 0.0f) {
        float d4 = spb[tid][4] - stb[tid][4];
        float d9 = spb[tid][9] - stb[tid][9];
        a0 = d4 * d4 + d9 * d9;
    }

    // per obj target box: max IOU over obj pred boxes -> coord/obj losses
    if (tid < 98 && sflag[tid >> 1] > 0.0f) {
        float X1 = qx1[tid], Y1 = qy1[tid], X2 = qx2[tid], Y2 = qy2[tid];
        float A  = qa[tid];
        float maxiou = 0.0f;
        int n = cnt;
        for (int ii = 0; ii < n; ii++) {
            int j = objlist[ii];
            float lx = fmaxf(px1[j], X1);
            float ly = fmaxf(py1[j], Y1);
            float rx = fminf(px2[j], X2);
            float ry = fminf(py2[j], Y2);
            float iw = fmaxf(rx - lx, 0.0f);
            float ih = fmaxf(ry - ly, 0.0f);
            float inter = iw * ih;
            float uni = pa[j] + A - inter;
            maxiou = fmaxf(maxiou, inter / (uni > 0.0f ? uni : 1.0f));
        }
        if (maxiou != 0.0f) {
            int cell = tid >> 1;
            int off  = (tid & 1) * 5;
            float dx = spb[cell][off]     - stb[cell][off];
            float dy = spb[cell][off + 1] - stb[cell][off + 1];
            float dw = sqrtf(spb[cell][off + 2]) - sqrtf(stb[cell][off + 2]);
            float dh = sqrtf(spb[cell][off + 3]) - sqrtf(stb[cell][off + 3]);
            a2 = dx * dx + dy * dy + dw * dw + dh * dh;
            float dc = spb[cell][off + 4] - stb[cell][off + 4];
            a3 = dc * dc;
        }
    }

    // block reduce 4 accumulators
    #pragma unroll
    for (int o = 16; o > 0; o >>= 1) {
        a0 += __shfl_down_sync(0xffffffffu, a0, o);
        a1 += __shfl_down_sync(0xffffffffu, a1, o);
        a2 += __shfl_down_sync(0xffffffffu, a2, o);
        a3 += __shfl_down_sync(0xffffffffu, a3, o);
    }
    int warp = tid >> 5, lane = tid & 31;
    if (lane == 0) {
        red[0][warp] = a0; red[1][warp] = a1; red[2][warp] = a2; red[3][warp] = a3;
    }
    __syncthreads();
    if (tid == 0) {
        float4 r;
        r.x = red[0][0] + red[0][1] + red[0][2] + red[0][3];
        r.y = red[1][0] + red[1][1] + red[1][2] + red[1][3];
        r.z = red[2][0] + red[2][1] + red[2][2] + red[2][3];
        r.w = red[3][0] + red[3][1] + red[3][2] + red[3][3];
        g_partials[b] = r;
        __threadfence();
        unsigned int t = atomicAdd(&g_done, 1u);
        amlast = (t == (unsigned int)(B - 1));
    }
    __syncthreads();

    // last block performs the final deterministic reduction
    if (amlast) {
        __threadfence();  // make all partial writes visible
        float s0 = 0.0f, s1 = 0.0f, s2 = 0.0f, s3 = 0.0f;
        #pragma unroll 4
        for (int i = tid; i < B; i += 128) {
            float4 v = g_partials[i];
            s0 += v.x; s1 += v.y; s2 += v.z; s3 += v.w;
        }
        #pragma unroll
        for (int o = 16; o > 0; o >>= 1) {
            s0 += __shfl_down_sync(0xffffffffu, s0, o);
            s1 += __shfl_down_sync(0xffffffffu, s1, o);
            s2 += __shfl_down_sync(0xffffffffu, s2, o);
            s3 += __shfl_down_sync(0xffffffffu, s3, o);
        }
        if (lane == 0) {
            red[0][warp] = s0; red[1][warp] = s1;
            red[2][warp] = s2; red[3][warp] = s3;
        }
        __syncthreads();
        if (tid == 0) {
            float t0 = red[0][0] + red[0][1] + red[0][2] + red[0][3];
            float t1 = red[1][0] + red[1][1] + red[1][2] + red[1][3];
            float t2 = red[2][0] + red[2][1] + red[2][2] + red[2][3];
            float t3 = red[3][0] + red[3][1] + red[3][2] + red[3][3];
            double invB  = 1.0 / (double)B;
            double cls   = (double)t1 * invB;
            double objl  = ((double)t3 + (double)t0 * 0.5) * invB;
            double coord = (double)t2 * 5.0 * invB;
            out[0] = (float)(cls + objl + coord);
            out[1] = (float)cls;
            out[2] = (float)objl;
            out[3] = (float)coord;
            g_done = 0;   // self-reset for next graph replay
        }
    }
}

extern "C" void kernel_launch(void* const* d_in, const int* in_sizes, int n_in,
                              void* d_out, int out_size)
{
    const float* pred = (const float*)d_in[0];
    const float* targ = (const float*)d_in[1];
    float* out = (float*)d_out;
    int B = in_sizes[0] / ELEMS;
    if (B > MAXB) B = MAXB;

    yolo_fused<<<B, 128>>>(pred, targ, out, B);
}

// round 9
// speedup vs baseline: 1.1709x; 1.1709x over previous
#include <cuda_runtime.h>

// YOLOv1 loss, GB300. pred/target [8192,7,7,30] f32 -> 4 f32 scalars.

#define ELEMS 1470
#define MAXB  8192

// per-batch partials: x=noobj, y=cls, z=coord, w=obj
__device__ float4 g_partials[MAXB];

__global__ void __launch_bounds__(128)
yolo_part(const float* __restrict__ pred, const float* __restrict__ targ)
{
    int b   = blockIdx.x;
    int tid = threadIdx.x;

    __shared__ __align__(8) float spb[49][10];   // pred ch0..9
    __shared__ __align__(8) float stb[49][10];   // targ ch0..9
    __shared__ __align__(8) float sd2[49][10];   // class pair d^2 sums (10 pairs)
    __shared__ float px1[98], py1[98], px2[98], py2[98], pa[98];
    __shared__ float qx1[98], qy1[98], qx2[98], qy2[98], qa[98];
    __shared__ int   objlist[98];
    __shared__ int   cnt;
    __shared__ float red[4][4];

    if (tid == 0) cnt = 0;

    const float2* p2 = reinterpret_cast<const float2*>(pred + (size_t)b * ELEMS);
    const float2* t2 = reinterpret_cast<const float2*>(targ + (size_t)b * ELEMS);

    // Lean streaming load: 735 float2 per tensor.
    // tid < 120: tid = c0*15 + k0 (c0 in 0..7, k0 in 0..14), computed ONCE.
    // iteration g: element i = g*120 + tid -> cell = g*8 + c0, pair k0.
    // k0 < 5  -> box channels 2k0,2k0+1 staged raw to smem.
    // k0 >= 5 -> class channels: store d1^2+d2^2 to sd2[cell][k0-5].
    if (tid < 120) {
        int c0 = tid / 15;
        int k0 = tid - c0 * 15;
        bool isbox = (k0 < 5);
        int chb = 2 * k0;           // box channel base (if isbox)
        int kc  = k0 - 5;           // class pair slot (if !isbox)

        #pragma unroll
        for (int g = 0; g < 6; g++) {
            int i    = g * 120 + tid;
            int cell = g * 8 + c0;
            float2 pv = p2[i];
            float2 tv = t2[i];
            if (isbox) {
                *reinterpret_cast<float2*>(&spb[cell][chb]) = pv;
                *reinterpret_cast<float2*>(&stb[cell][chb]) = tv;
            } else {
                float d1 = pv.x - tv.x;
                float d2 = pv.y - tv.y;
                sd2[cell][kc] = d1 * d1 + d2 * d2;
            }
        }
    }
    // remainder: elements 720..734 = cell 48, pairs 0..14
    if (tid < 15) {
        int i = 720 + tid;
        float2 pv = p2[i];
        float2 tv = t2[i];
        if (tid < 5) {
            *reinterpret_cast<float2*>(&spb[48][2 * tid]) = pv;
            *reinterpret_cast<float2*>(&stb[48][2 * tid]) = tv;
        } else {
            float d1 = pv.x - tv.x;
            float d2 = pv.y - tv.y;
            sd2[48][tid - 5] = d1 * d1 + d2 * d2;
        }
    }
    __syncthreads();

    float a0 = 0.0f, a1 = 0.0f, a2 = 0.0f, a3 = 0.0f;  // noobj, cls, coord, obj

    // per-box xyxy + area, compacted obj-box list
    if (tid < 98) {
        int cell = tid >> 1;
        int off  = (tid & 1) * 5;
        {
            float cx = spb[cell][off],     cy = spb[cell][off + 1];
            float w  = spb[cell][off + 2], h  = spb[cell][off + 3];
            float x1 = cx - w * 0.5f, y1 = cy - h * 0.5f;
            float x2 = cx + w * 0.5f, y2 = cy + h * 0.5f;
            px1[tid] = x1; py1[tid] = y1; px2[tid] = x2; py2[tid] = y2;
            pa[tid]  = (x2 - x1) * (y2 - y1);
        }
        {
            float cx = stb[cell][off],     cy = stb[cell][off + 1];
            float w  = stb[cell][off + 2], h  = stb[cell][off + 3];
            float x1 = cx - w * 0.5f, y1 = cy - h * 0.5f;
            float x2 = cx + w * 0.5f, y2 = cy + h * 0.5f;
            qx1[tid] = x1; qy1[tid] = y1; qx2[tid] = x2; qy2[tid] = y2;
            qa[tid]  = (x2 - x1) * (y2 - y1);
        }
        if (stb[cell][4] > 0.0f) objlist[atomicAdd(&cnt, 1)] = tid;
    }
    __syncthreads();

    // per-cell: noobj confidence loss OR class loss (masked by obj flag)
    if (tid < 49) {
        if (stb[tid][4] == 0.0f) {
            float d4 = spb[tid][4] - stb[tid][4];
            float d9 = spb[tid][9] - stb[tid][9];
            a0 = d4 * d4 + d9 * d9;
        } else {
            const float2* c2 = reinterpret_cast<const float2*>(sd2[tid]);
            float s = 0.0f;
            #pragma unroll
            for (int q = 0; q < 5; q++) {
                float2 v = c2[q];
                s += v.x + v.y;
            }
            a1 = s;
        }
    }

    // per obj target box: max IOU over obj pred boxes -> coord/obj losses
    if (tid < 98 && stb[tid >> 1][4] > 0.0f) {
        float X1 = qx1[tid], Y1 = qy1[tid], X2 = qx2[tid], Y2 = qy2[tid];
        float A  = qa[tid];
        float maxiou = 0.0f;
        int n = cnt;
        for (int ii = 0; ii < n; ii++) {
            int j = objlist[ii];
            float lx = fmaxf(px1[j], X1);
            float ly = fmaxf(py1[j], Y1);
            float rx = fminf(px2[j], X2);
            float ry = fminf(py2[j], Y2);
            float iw = fmaxf(rx - lx, 0.0f);
            float ih = fmaxf(ry - ly, 0.0f);
            float inter = iw * ih;
            float uni = pa[j] + A - inter;
            maxiou = fmaxf(maxiou, inter / (uni > 0.0f ? uni : 1.0f));
        }
        if (maxiou != 0.0f) {
            int cell = tid >> 1;
            int off  = (tid & 1) * 5;
            float dx = spb[cell][off]     - stb[cell][off];
            float dy = spb[cell][off + 1] - stb[cell][off + 1];
            float dw = sqrtf(spb[cell][off + 2]) - sqrtf(stb[cell][off + 2]);
            float dh = sqrtf(spb[cell][off + 3]) - sqrtf(stb[cell][off + 3]);
            a2 = dx * dx + dy * dy + dw * dw + dh * dh;
            float dc = spb[cell][off + 4] - stb[cell][off + 4];
            a3 = dc * dc;
        }
    }

    // block reduce 4 accumulators across 128 threads
    #pragma unroll
    for (int o = 16; o > 0; o >>= 1) {
        a0 += __shfl_down_sync(0xffffffffu, a0, o);
        a1 += __shfl_down_sync(0xffffffffu, a1, o);
        a2 += __shfl_down_sync(0xffffffffu, a2, o);
        a3 += __shfl_down_sync(0xffffffffu, a3, o);
    }
    int warp = tid >> 5, lane = tid & 31;
    if (lane == 0) {
        red[0][warp] = a0; red[1][warp] = a1; red[2][warp] = a2; red[3][warp] = a3;
    }
    __syncthreads();
    if (tid == 0) {
        float4 r;
        r.x = red[0][0] + red[0][1] + red[0][2] + red[0][3];
        r.y = red[1][0] + red[1][1] + red[1][2] + red[1][3];
        r.z = red[2][0] + red[2][1] + red[2][2] + red[2][3];
        r.w = red[3][0] + red[3][1] + red[3][2] + red[3][3];
        g_partials[b] = r;
    }
}

__global__ void __launch_bounds__(1024)
yolo_reduce(int B, float* __restrict__ out)
{
    int tid = threadIdx.x;
    float s0 = 0.0f, s1 = 0.0f, s2 = 0.0f, s3 = 0.0f;
    #pragma unroll 8
    for (int i = tid; i < B; i += 1024) {
        float4 v = g_partials[i];
        s0 += v.x; s1 += v.y; s2 += v.z; s3 += v.w;
    }
    #pragma unroll
    for (int o = 16; o > 0; o >>= 1) {
        s0 += __shfl_down_sync(0xffffffffu, s0, o);
        s1 += __shfl_down_sync(0xffffffffu, s1, o);
        s2 += __shfl_down_sync(0xffffffffu, s2, o);
        s3 += __shfl_down_sync(0xffffffffu, s3, o);
    }
    __shared__ float sm[32][4];
    int warp = tid >> 5, lane = tid & 31;
    if (lane == 0) {
        sm[warp][0] = s0; sm[warp][1] = s1; sm[warp][2] = s2; sm[warp][3] = s3;
    }
    __syncthreads();
    if (tid < 32) {
        float t0 = sm[tid][0], t1 = sm[tid][1], t2 = sm[tid][2], t3 = sm[tid][3];
        #pragma unroll
        for (int o = 16; o > 0; o >>= 1) {
            t0 += __shfl_down_sync(0xffffffffu, t0, o);
            t1 += __shfl_down_sync(0xffffffffu, t1, o);
            t2 += __shfl_down_sync(0xffffffffu, t2, o);
            t3 += __shfl_down_sync(0xffffffffu, t3, o);
        }
        if (tid == 0) {
            double invB  = 1.0 / (double)B;
            double cls   = (double)t1 * invB;
            double objl  = ((double)t3 + (double)t0 * 0.5) * invB;
            double coord = (double)t2 * 5.0 * invB;
            out[0] = (float)(cls + objl + coord);
            out[1] = (float)cls;
            out[2] = (float)objl;
            out[3] = (float)coord;
        }
    }
}

extern "C" void kernel_launch(void* const* d_in, const int* in_sizes, int n_in,
                              void* d_out, int out_size)
{
    const float* pred = (const float*)d_in[0];
    const float* targ = (const float*)d_in[1];
    float* out = (float*)d_out;
    int B = in_sizes[0] / ELEMS;
    if (B > MAXB) B = MAXB;

    yolo_part<<<B, 128>>>(pred, targ);
    yolo_reduce<<<1, 1024>>>(B, out);
}

// round 13
// speedup vs baseline: 2.2276x; 1.9024x over previous
#include <cuda_runtime.h>

// YOLOv1 loss, GB300. pred/target [8192,7,7,30] f32 -> 4 f32 scalars.

#define ELEMS 1470
#define MAXB  8192

// per-batch partials: x=noobj, y=cls, z=coord, w=obj
__device__ float4 g_partials[MAXB];

__global__ void __launch_bounds__(128)
yolo_part(const float* __restrict__ pred, const float* __restrict__ targ)
{
    int b   = blockIdx.x;
    int tid = threadIdx.x;

    __shared__ __align__(8) float spb[49][10];   // pred ch0..9
    __shared__ __align__(8) float stb[49][10];   // targ ch0..9
    __shared__ __align__(8) float sd2[49][10];   // class pair d^2 sums (10 pairs)
    __shared__ float px1[98], py1[98], px2[98], py2[98];
    __shared__ float qx1[98], qy1[98], qx2[98], qy2[98];
    __shared__ int   objlist[98];
    __shared__ int   cnt;
    __shared__ float red[4][4];

    if (tid == 0) cnt = 0;

    const float2* p2 = reinterpret_cast<const float2*>(pred + (size_t)b * ELEMS);
    const float2* t2 = reinterpret_cast<const float2*>(targ + (size_t)b * ELEMS);

    // Lean streaming load: 735 float2 per tensor.
    // tid < 120: tid = c0*15 + k0, computed ONCE; iteration g handles
    // element g*120+tid -> cell g*8+c0, pair k0.
    if (tid < 120) {
        int c0 = tid / 15;
        int k0 = tid - c0 * 15;
        bool isbox = (k0 < 5);
        int chb = 2 * k0;
        int kc  = k0 - 5;

        #pragma unroll
        for (int g = 0; g < 6; g++) {
            int i    = g * 120 + tid;
            int cell = g * 8 + c0;
            float2 pv = p2[i];
            float2 tv = t2[i];
            if (isbox) {
                *reinterpret_cast<float2*>(&spb[cell][chb]) = pv;
                *reinterpret_cast<float2*>(&stb[cell][chb]) = tv;
            } else {
                float d1 = pv.x - tv.x;
                float d2 = pv.y - tv.y;
                sd2[cell][kc] = d1 * d1 + d2 * d2;
            }
        }
    }
    if (tid < 15) {
        int i = 720 + tid;
        float2 pv = p2[i];
        float2 tv = t2[i];
        if (tid < 5) {
            *reinterpret_cast<float2*>(&spb[48][2 * tid]) = pv;
            *reinterpret_cast<float2*>(&stb[48][2 * tid]) = tv;
        } else {
            float d1 = pv.x - tv.x;
            float d2 = pv.y - tv.y;
            sd2[48][tid - 5] = d1 * d1 + d2 * d2;
        }
    }
    __syncthreads();

    float a0 = 0.0f, a1 = 0.0f, a2 = 0.0f, a3 = 0.0f;  // noobj, cls, coord, obj

    // per-box xyxy, compacted obj-box list (areas no longer needed:
    // cmask reduces to any-overlap, see below)
    if (tid < 98) {
        int cell = tid >> 1;
        int off  = (tid & 1) * 5;
        {
            float cx = spb[cell][off],     cy = spb[cell][off + 1];
            float w  = spb[cell][off + 2], h  = spb[cell][off + 3];
            px1[tid] = cx - w * 0.5f; py1[tid] = cy - h * 0.5f;
            px2[tid] = cx + w * 0.5f; py2[tid] = cy + h * 0.5f;
        }
        {
            float cx = stb[cell][off],     cy = stb[cell][off + 1];
            float w  = stb[cell][off + 2], h  = stb[cell][off + 3];
            qx1[tid] = cx - w * 0.5f; qy1[tid] = cy - h * 0.5f;
            qx2[tid] = cx + w * 0.5f; qy2[tid] = cy + h * 0.5f;
        }
        if (stb[cell][4] > 0.0f) objlist[atomicAdd(&cnt, 1)] = tid;
    }
    __syncthreads();

    // per-cell: noobj confidence loss OR class loss
    if (tid < 49) {
        if (stb[tid][4] == 0.0f) {
            float d4 = spb[tid][4] - stb[tid][4];
            float d9 = spb[tid][9] - stb[tid][9];
            a0 = d4 * d4 + d9 * d9;
        } else {
            const float2* c2 = reinterpret_cast<const float2*>(sd2[tid]);
            float s = 0.0f;
            #pragma unroll
            for (int q = 0; q < 5; q++) {
                float2 v = c2[q];
                s += v.x + v.y;
            }
            a1 = s;
        }
    }

    // cmask: reference uses only (max_iou != 0). With w,h >= 0.05 all areas
    // are > 0, so union > 0 and iou > 0 <=> intersection > 0 <=> overlap.
    // Exact boolean equivalence -> any-overlap test with early exit.
    if (tid < 98 && stb[tid >> 1][4] > 0.0f) {
        float X1 = qx1[tid], Y1 = qy1[tid], X2 = qx2[tid], Y2 = qy2[tid];
        bool hit = false;
        int n = cnt;
        for (int ii = 0; ii < n; ii++) {
            int j = objlist[ii];
            float iw = fminf(px2[j], X2) - fmaxf(px1[j], X1);
            float ih = fminf(py2[j], Y2) - fmaxf(py1[j], Y1);
            if (iw > 0.0f && ih > 0.0f) { hit = true; break; }
        }
        if (hit) {
            int cell = tid >> 1;
            int off  = (tid & 1) * 5;
            float dx = spb[cell][off]     - stb[cell][off];
            float dy = spb[cell][off + 1] - stb[cell][off + 1];
            float dw = sqrtf(spb[cell][off + 2]) - sqrtf(stb[cell][off + 2]);
            float dh = sqrtf(spb[cell][off + 3]) - sqrtf(stb[cell][off + 3]);
            a2 = dx * dx + dy * dy + dw * dw + dh * dh;
            float dc = spb[cell][off + 4] - stb[cell][off + 4];
            a3 = dc * dc;
        }
    }

    // block reduce 4 accumulators across 128 threads
    #pragma unroll
    for (int o = 16; o > 0; o >>= 1) {
        a0 += __shfl_down_sync(0xffffffffu, a0, o);
        a1 += __shfl_down_sync(0xffffffffu, a1, o);
        a2 += __shfl_down_sync(0xffffffffu, a2, o);
        a3 += __shfl_down_sync(0xffffffffu, a3, o);
    }
    int warp = tid >> 5, lane = tid & 31;
    if (lane == 0) {
        red[0][warp] = a0; red[1][warp] = a1; red[2][warp] = a2; red[3][warp] = a3;
    }
    __syncthreads();
    if (tid == 0) {
        float4 r;
        r.x = red[0][0] + red[0][1] + red[0][2] + red[0][3];
        r.y = red[1][0] + red[1][1] + red[1][2] + red[1][3];
        r.z = red[2][0] + red[2][1] + red[2][2] + red[2][3];
        r.w = red[3][0] + red[3][1] + red[3][2] + red[3][3];
        g_partials[b] = r;
    }
}

__global__ void __launch_bounds__(1024)
yolo_reduce(int B, float* __restrict__ out)
{
    int tid = threadIdx.x;
    float s0 = 0.0f, s1 = 0.0f, s2 = 0.0f, s3 = 0.0f;
    #pragma unroll 8
    for (int i = tid; i < B; i += 1024) {
        float4 v = g_partials[i];
        s0 += v.x; s1 += v.y; s2 += v.z; s3 += v.w;
    }
    #pragma unroll
    for (int o = 16; o > 0; o >>= 1) {
        s0 += __shfl_down_sync(0xffffffffu, s0, o);
        s1 += __shfl_down_sync(0xffffffffu, s1, o);
        s2 += __shfl_down_sync(0xffffffffu, s2, o);
        s3 += __shfl_down_sync(0xffffffffu, s3, o);
    }
    __shared__ float sm[32][4];
    int warp = tid >> 5, lane = tid & 31;
    if (lane == 0) {
        sm[warp][0] = s0; sm[warp][1] = s1; sm[warp][2] = s2; sm[warp][3] = s3;
    }
    __syncthreads();
    if (tid < 32) {
        float t0 = sm[tid][0], t1 = sm[tid][1], t2 = sm[tid][2], t3 = sm[tid][3];
        #pragma unroll
        for (int o = 16; o > 0; o >>= 1) {
            t0 += __shfl_down_sync(0xffffffffu, t0, o);
            t1 += __shfl_down_sync(0xffffffffu, t1, o);
            t2 += __shfl_down_sync(0xffffffffu, t2, o);
            t3 += __shfl_down_sync(0xffffffffu, t3, o);
        }
        if (tid == 0) {
            double invB  = 1.0 / (double)B;
            double cls   = (double)t1 * invB;
            double objl  = ((double)t3 + (double)t0 * 0.5) * invB;
            double coord = (double)t2 * 5.0 * invB;
            out[0] = (float)(cls + objl + coord);
            out[1] = (float)cls;
            out[2] = (float)objl;
            out[3] = (float)coord;
        }
    }
}

// Instrumentation: pad launches-per-replay to 5 so ncu's "-s 5 -c 1"
// lands on yolo_part (the correctness call consumes indices 0..4;
// index 5 = first launch of the first timed replay = yolo_part).
__device__ int g_sink;
__global__ void yolo_pad(int v) { if (v == -12345) g_sink = v; }

extern "C" void kernel_launch(void* const* d_in, const int* in_sizes, int n_in,
                              void* d_out, int out_size)
{
    const float* pred = (const float*)d_in[0];
    const float* targ = (const float*)d_in[1];
    float* out = (float*)d_out;
    int B = in_sizes[0] / ELEMS;
    if (B > MAXB) B = MAXB;

    yolo_part<<<B, 128>>>(pred, targ);
    yolo_reduce<<<1, 1024>>>(B, out);
    yolo_pad<<<1, 32>>>(1);
    yolo_pad<<<1, 32>>>(2);
    yolo_pad<<<1, 32>>>(3);
}

// round 14
// speedup vs baseline: 2.4061x; 1.0801x over previous
#include <cuda_runtime.h>

// YOLOv1 loss, GB300. pred/target [8192,7,7,30] f32 -> 4 f32 scalars.

#define ELEMS 1470
#define MAXB  8192

// per-batch partials: x=noobj, y=cls, z=coord, w=obj
__device__ float4 g_partials[MAXB];
__device__ float4 g_stage[32];

__global__ void __launch_bounds__(128)
yolo_part(const float* __restrict__ pred, const float* __restrict__ targ)
{
    int b   = blockIdx.x;
    int tid = threadIdx.x;

    __shared__ __align__(8) float spb[49][10];   // pred ch0..9
    __shared__ __align__(8) float stb[49][10];   // targ ch0..9
    __shared__ __align__(8) float sd2[49][10];   // class pair d^2 sums (10 pairs)
    __shared__ float px1[98], py1[98], px2[98], py2[98];
    __shared__ float qx1[98], qy1[98], qx2[98], qy2[98];
    __shared__ int   objlist[98];
    __shared__ int   cnt;
    __shared__ float red[4][4];

    if (tid == 0) cnt = 0;

    const float2* p2 = reinterpret_cast<const float2*>(pred + (size_t)b * ELEMS);
    const float2* t2 = reinterpret_cast<const float2*>(targ + (size_t)b * ELEMS);

    // Lean streaming load: 735 float2 per tensor.
    // tid < 120: tid = c0*15 + k0, computed ONCE; iteration g handles
    // element g*120+tid -> cell g*8+c0, pair k0.
    if (tid < 120) {
        int c0 = tid / 15;
        int k0 = tid - c0 * 15;
        bool isbox = (k0 < 5);
        int chb = 2 * k0;
        int kc  = k0 - 5;

        #pragma unroll
        for (int g = 0; g < 6; g++) {
            int i    = g * 120 + tid;
            int cell = g * 8 + c0;
            float2 pv = p2[i];
            float2 tv = t2[i];
            if (isbox) {
                *reinterpret_cast<float2*>(&spb[cell][chb]) = pv;
                *reinterpret_cast<float2*>(&stb[cell][chb]) = tv;
            } else {
                float d1 = pv.x - tv.x;
                float d2 = pv.y - tv.y;
                sd2[cell][kc] = d1 * d1 + d2 * d2;
            }
        }
    }
    if (tid < 15) {
        int i = 720 + tid;
        float2 pv = p2[i];
        float2 tv = t2[i];
        if (tid < 5) {
            *reinterpret_cast<float2*>(&spb[48][2 * tid]) = pv;
            *reinterpret_cast<float2*>(&stb[48][2 * tid]) = tv;
        } else {
            float d1 = pv.x - tv.x;
            float d2 = pv.y - tv.y;
            sd2[48][tid - 5] = d1 * d1 + d2 * d2;
        }
    }
    __syncthreads();

    float a0 = 0.0f, a1 = 0.0f, a2 = 0.0f, a3 = 0.0f;  // noobj, cls, coord, obj

    // per-box xyxy, compacted obj-box list
    if (tid < 98) {
        int cell = tid >> 1;
        int off  = (tid & 1) * 5;
        {
            float cx = spb[cell][off],     cy = spb[cell][off + 1];
            float w  = spb[cell][off + 2], h  = spb[cell][off + 3];
            px1[tid] = cx - w * 0.5f; py1[tid] = cy - h * 0.5f;
            px2[tid] = cx + w * 0.5f; py2[tid] = cy + h * 0.5f;
        }
        {
            float cx = stb[cell][off],     cy = stb[cell][off + 1];
            float w  = stb[cell][off + 2], h  = stb[cell][off + 3];
            qx1[tid] = cx - w * 0.5f; qy1[tid] = cy - h * 0.5f;
            qx2[tid] = cx + w * 0.5f; qy2[tid] = cy + h * 0.5f;
        }
        if (stb[cell][4] > 0.0f) objlist[atomicAdd(&cnt, 1)] = tid;
    }
    __syncthreads();

    // per-cell: noobj confidence loss OR class loss
    if (tid < 49) {
        if (stb[tid][4] == 0.0f) {
            float d4 = spb[tid][4] - stb[tid][4];
            float d9 = spb[tid][9] - stb[tid][9];
            a0 = d4 * d4 + d9 * d9;
        } else {
            const float2* c2 = reinterpret_cast<const float2*>(sd2[tid]);
            float s = 0.0f;
            #pragma unroll
            for (int q = 0; q < 5; q++) {
                float2 v = c2[q];
                s += v.x + v.y;
            }
            a1 = s;
        }
    }

    // cmask: reference uses only (max_iou != 0). With w,h >= 0.05 all areas
    // are > 0, so union > 0 and iou > 0 <=> intersection > 0 <=> overlap.
    // Exact boolean equivalence -> any-overlap test with early exit.
    if (tid < 98 && stb[tid >> 1][4] > 0.0f) {
        float X1 = qx1[tid], Y1 = qy1[tid], X2 = qx2[tid], Y2 = qy2[tid];
        bool hit = false;
        int n = cnt;
        for (int ii = 0; ii < n; ii++) {
            int j = objlist[ii];
            float iw = fminf(px2[j], X2) - fmaxf(px1[j], X1);
            float ih = fminf(py2[j], Y2) - fmaxf(py1[j], Y1);
            if (iw > 0.0f && ih > 0.0f) { hit = true; break; }
        }
        if (hit) {
            int cell = tid >> 1;
            int off  = (tid & 1) * 5;
            float dx = spb[cell][off]     - stb[cell][off];
            float dy = spb[cell][off + 1] - stb[cell][off + 1];
            float dw = sqrtf(spb[cell][off + 2]) - sqrtf(stb[cell][off + 2]);
            float dh = sqrtf(spb[cell][off + 3]) - sqrtf(stb[cell][off + 3]);
            a2 = dx * dx + dy * dy + dw * dw + dh * dh;
            float dc = spb[cell][off + 4] - stb[cell][off + 4];
            a3 = dc * dc;
        }
    }

    // block reduce 4 accumulators across 128 threads
    #pragma unroll
    for (int o = 16; o > 0; o >>= 1) {
        a0 += __shfl_down_sync(0xffffffffu, a0, o);
        a1 += __shfl_down_sync(0xffffffffu, a1, o);
        a2 += __shfl_down_sync(0xffffffffu, a2, o);
        a3 += __shfl_down_sync(0xffffffffu, a3, o);
    }
    int warp = tid >> 5, lane = tid & 31;
    if (lane == 0) {
        red[0][warp] = a0; red[1][warp] = a1; red[2][warp] = a2; red[3][warp] = a3;
    }
    __syncthreads();
    if (tid == 0) {
        float4 r;
        r.x = red[0][0] + red[0][1] + red[0][2] + red[0][3];
        r.y = red[1][0] + red[1][1] + red[1][2] + red[1][3];
        r.z = red[2][0] + red[2][1] + red[2][2] + red[2][3];
        r.w = red[3][0] + red[3][1] + red[3][2] + red[3][3];
        g_partials[b] = r;
    }
}

// Stage 1: 32 blocks x 256 threads; block i sums partials [i*256, i*256+256).
__global__ void __launch_bounds__(256)
yolo_red1(void)
{
    int tid = threadIdx.x;
    int idx = blockIdx.x * 256 + tid;
    float4 v = g_partials[idx];
    float s0 = v.x, s1 = v.y, s2 = v.z, s3 = v.w;
    #pragma unroll
    for (int o = 16; o > 0; o >>= 1) {
        s0 += __shfl_down_sync(0xffffffffu, s0, o);
        s1 += __shfl_down_sync(0xffffffffu, s1, o);
        s2 += __shfl_down_sync(0xffffffffu, s2, o);
        s3 += __shfl_down_sync(0xffffffffu, s3, o);
    }
    __shared__ float sm[8][4];
    int warp = tid >> 5, lane = tid & 31;
    if (lane == 0) {
        sm[warp][0] = s0; sm[warp][1] = s1; sm[warp][2] = s2; sm[warp][3] = s3;
    }
    __syncthreads();
    if (tid == 0) {
        float t0 = 0, t1 = 0, t2 = 0, t3 = 0;
        #pragma unroll
        for (int w = 0; w < 8; w++) {
            t0 += sm[w][0]; t1 += sm[w][1]; t2 += sm[w][2]; t3 += sm[w][3];
        }
        g_stage[blockIdx.x] = make_float4(t0, t1, t2, t3);
    }
}

// Stage 2: one warp sums the 32 stage results and finalizes.
__global__ void __launch_bounds__(32)
yolo_red2(int B, float* __restrict__ out)
{
    int tid = threadIdx.x;
    float4 v = g_stage[tid];
    float s0 = v.x, s1 = v.y, s2 = v.z, s3 = v.w;
    #pragma unroll
    for (int o = 16; o > 0; o >>= 1) {
        s0 += __shfl_down_sync(0xffffffffu, s0, o);
        s1 += __shfl_down_sync(0xffffffffu, s1, o);
        s2 += __shfl_down_sync(0xffffffffu, s2, o);
        s3 += __shfl_down_sync(0xffffffffu, s3, o);
    }
    if (tid == 0) {
        double invB  = 1.0 / (double)B;
        double cls   = (double)s1 * invB;
        double objl  = ((double)s3 + (double)s0 * 0.5) * invB;
        double coord = (double)s2 * 5.0 * invB;
        out[0] = (float)(cls + objl + coord);
        out[1] = (float)cls;
        out[2] = (float)objl;
        out[3] = (float)coord;
    }
}

extern "C" void kernel_launch(void* const* d_in, const int* in_sizes, int n_in,
                              void* d_out, int out_size)
{
    const float* pred = (const float*)d_in[0];
    const float* targ = (const float*)d_in[1];
    float* out = (float*)d_out;
    int B = in_sizes[0] / ELEMS;
    if (B > MAXB) B = MAXB;

    yolo_part<<<B, 128>>>(pred, targ);
    yolo_red1<<<32, 256>>>();
    yolo_red2<<<1, 32>>>(B, out);
}